// round 3
// baseline (speedup 1.0000x reference)
#include <cuda_runtime.h>
#include <math.h>

// Problem dims
#define T_    512
#define B_    64
#define F_    256
#define E_    512
#define G4E   2048   // 4*E
#define G4F   1024   // 4*F
#define DECIN 1024   // 2*E

typedef unsigned long long u64;

// ---------------- device scratch (static; no allocations) ----------------
__device__ float g_xproj[2][T_][B_][G4E];     // [dir][t][b][col], col = u*4+gate
__device__ float g_WihIl[2][G4E][F_];         // interleaved enc Wih
__device__ float g_bIl[2][G4E];
__device__ float g_WhhIl[2][E_][E_][4];       // [dir][u][k][gate]
__device__ float g_h[2][2][E_][B_];           // [dir][phase][u][b]  ping-pong
__device__ float g_WdecIhIl[F_][DECIN][4];    // [f][k][gate]
__device__ float g_bdecIl[F_][4];
__device__ float g_WdecHhIl[F_][F_][4];       // [f][k][gate]
__device__ float g_xp0[B_][F_][4];            // decoder constant input proj
__device__ float g_hd[2][F_][B_];             // decoder h ping-pong
__device__ unsigned g_bar_enc;
__device__ unsigned g_bar_dec;

__device__ __forceinline__ float sigm(float x) { return 1.0f / (1.0f + expf(-x)); }

__device__ __forceinline__ u64 dup2(float x) {
    u64 r; asm("mov.b64 %0, {%1, %1};" : "=l"(r) : "f"(x)); return r;
}
__device__ __forceinline__ void fma2(u64& d, u64 a, u64 b) {
    asm("fma.rn.f32x2 %0, %1, %2, %0;" : "+l"(d) : "l"(a), "l"(b));
}
__device__ __forceinline__ float2 unpk(u64 v) {
    float2 r; asm("mov.b64 {%0, %1}, %2;" : "=f"(r.x), "=f"(r.y) : "l"(v)); return r;
}

// ---------------- prep: interleave weights, zero states ----------------
__global__ void prep_kernel(const float* wihf, const float* whhf, const float* bf,
                            const float* wihb, const float* whhb, const float* bb,
                            const float* dwih, const float* dwhh, const float* db)
{
    int tid = blockIdx.x * blockDim.x + threadIdx.x;
    int stride = gridDim.x * blockDim.x;

    if (tid == 0) { g_bar_enc = 0u; g_bar_dec = 0u; }

    // enc Wih interleave: [2][2048][256]
    for (int i = tid; i < 2 * G4E * F_; i += stride) {
        int d = i / (G4E * F_);
        int r = i - d * (G4E * F_);
        int col = r / F_;
        int k = r - col * F_;
        int u = col >> 2, g = col & 3;
        const float* src = d ? wihb : wihf;
        g_WihIl[d][col][k] = src[(g * E_ + u) * F_ + k];
    }
    // enc bias interleave
    for (int i = tid; i < 2 * G4E; i += stride) {
        int d = i >> 11, col = i & (G4E - 1);
        int u = col >> 2, g = col & 3;
        g_bIl[d][col] = (d ? bb : bf)[g * E_ + u];
    }
    // enc Whh interleave: [2][512][512][4]
    for (int i = tid; i < 2 * E_ * E_ * 4; i += stride) {
        int d = i / (E_ * E_ * 4);
        int r = i - d * (E_ * E_ * 4);
        int u = r / (E_ * 4);
        int k = (r >> 2) & (E_ - 1);
        int g = r & 3;
        g_WhhIl[d][u][k][g] = (d ? whhb : whhf)[(g * E_ + u) * E_ + k];
    }
    // dec Wih interleave: [256][1024][4]
    for (int i = tid; i < F_ * DECIN * 4; i += stride) {
        int f = i / (DECIN * 4);
        int k = (i >> 2) & (DECIN - 1);
        int g = i & 3;
        g_WdecIhIl[f][k][g] = dwih[(g * F_ + f) * DECIN + k];
    }
    for (int i = tid; i < G4F; i += stride) {
        int f = i >> 2, g = i & 3;
        g_bdecIl[f][g] = db[g * F_ + f];
    }
    // dec Whh interleave: [256][256][4]
    for (int i = tid; i < F_ * F_ * 4; i += stride) {
        int f = i / (F_ * 4);
        int k = (i >> 2) & (F_ - 1);
        int g = i & 3;
        g_WdecHhIl[f][k][g] = dwhh[(g * F_ + f) * F_ + k];
    }
    // zero states
    for (int i = tid; i < 2 * 2 * E_ * B_; i += stride) ((float*)g_h)[i] = 0.0f;
    for (int i = tid; i < 2 * F_ * B_; i += stride)     ((float*)g_hd)[i] = 0.0f;
}

// ---------------- xproj GEMM (f32x2): M=32768, N=2048, K=256 ----------------
__global__ void __launch_bounds__(256) xproj_gemm(const float* __restrict__ seq)
{
    const int dir = blockIdx.z;
    const int m0 = blockIdx.y * 128;
    const int n0 = blockIdx.x * 64;
    const int tid = threadIdx.x;
    const int ty = tid >> 4;   // 0..15
    const int tx = tid & 15;   // 0..15

    __shared__ float As[16][128];
    __shared__ float Bs[16][64];

    u64 acc[8][2];
#pragma unroll
    for (int i = 0; i < 8; i++) { acc[i][0] = 0ull; acc[i][1] = 0ull; }

    const float* W = &g_WihIl[dir][0][0];

    for (int k0 = 0; k0 < F_; k0 += 16) {
#pragma unroll
        for (int p = 0; p < 2; p++) {
            int idx = tid + p * 256;
            int row = idx >> 2, kq = idx & 3;
            int m = m0 + row;
            int tt = m >> 6, b = m & 63;
            int ts = dir ? (T_ - 1 - tt) : tt;
            float4 v = *(const float4*)&seq[((size_t)ts * B_ + b) * F_ + k0 + kq * 4];
            As[kq * 4 + 0][row] = v.x;
            As[kq * 4 + 1][row] = v.y;
            As[kq * 4 + 2][row] = v.z;
            As[kq * 4 + 3][row] = v.w;
        }
        {
            int col = tid >> 2, kq = tid & 3;
            float4 v = *(const float4*)&W[(size_t)(n0 + col) * F_ + k0 + kq * 4];
            Bs[kq * 4 + 0][col] = v.x;
            Bs[kq * 4 + 1][col] = v.y;
            Bs[kq * 4 + 2][col] = v.z;
            Bs[kq * 4 + 3][col] = v.w;
        }
        __syncthreads();
#pragma unroll
        for (int kk = 0; kk < 16; kk++) {
            float4 a0 = *(const float4*)&As[kk][ty * 8];
            float4 a1 = *(const float4*)&As[kk][ty * 8 + 4];
            const u64* bp = (const u64*)&Bs[kk][tx * 4];
            u64 b01 = bp[0], b23 = bp[1];
            float av[8] = {a0.x, a0.y, a0.z, a0.w, a1.x, a1.y, a1.z, a1.w};
#pragma unroll
            for (int i = 0; i < 8; i++) {
                u64 ad = dup2(av[i]);
                fma2(acc[i][0], ad, b01);
                fma2(acc[i][1], ad, b23);
            }
        }
        __syncthreads();
    }

    float4 bias = *(const float4*)&g_bIl[dir][n0 + tx * 4];
    float* out = &g_xproj[0][0][0][0];
#pragma unroll
    for (int i = 0; i < 8; i++) {
        size_t m = (size_t)m0 + ty * 8 + i;
        float2 c01 = unpk(acc[i][0]);
        float2 c23 = unpk(acc[i][1]);
        float4 o;
        o.x = c01.x + bias.x;
        o.y = c01.y + bias.y;
        o.z = c23.x + bias.z;
        o.w = c23.y + bias.w;
        *(float4*)&out[((size_t)dir * 32768 + m) * (size_t)G4E + n0 + tx * 4] = o;
    }
}

// ---------------- persistent encoder: all 512 steps, grid barrier ----------------
// grid = 128 CTAs (64/dir, 8 units each), 128 threads.
// Warp covers 2 units; lane l: unit = 2w + (l>>4), batches b0..b0+3 with b0=(l&15)*4.
// dynamic smem: ws 64KB (full Whh slice, loaded once) + hs 128KB (full h per step).
__global__ void __launch_bounds__(128) enc_persist()
{
    extern __shared__ float sm[];
    float* ws = sm;            // 8 units * 512 k * 4 gates = 16384 floats
    float* hs = sm + 16384;    // 512 k * 64 b = 32768 floats

    const int dir = (int)(blockIdx.x >> 6);
    const int u0 = (int)(blockIdx.x & 63) * 8;
    const int w = threadIdx.x >> 5;
    const int l = threadIdx.x & 31;
    const int uu = 2 * w + (l >> 4);
    const int u = u0 + uu;
    const int b0 = (l & 15) * 4;

    // load Whh slice once: 4096 float4, i = su*512 + k
    for (int i = threadIdx.x; i < 4096; i += 128) {
        int su = i >> 9, k = i & 511;
        ((float4*)ws)[i] = *(const float4*)&g_WhhIl[dir][u0 + su][k][0];
    }

    const float* wp = ws + uu * 2048;
    float c0 = 0.f, c1 = 0.f, c2 = 0.f, c3 = 0.f;

    for (int t = 0; t < T_; t++) {
        const int ph = t & 1;

        // prefetch xproj (constant data, read-once; issue early, consume in epilogue)
        const float4 xpa = *(const float4*)&g_xproj[dir][t][b0 + 0][u << 2];
        const float4 xpb = *(const float4*)&g_xproj[dir][t][b0 + 1][u << 2];
        const float4 xpc = *(const float4*)&g_xproj[dir][t][b0 + 2][u << 2];
        const float4 xpd = *(const float4*)&g_xproj[dir][t][b0 + 3][u << 2];

        // stage h into smem (L2-coherent loads: buffer alternates every step)
        const float4* hsrc = (const float4*)&g_h[dir][ph][0][0];
        for (int i = threadIdx.x; i < 8192; i += 128)
            ((float4*)hs)[i] = __ldcg(hsrc + i);
        __syncthreads();

        u64 ai0 = 0, ai1 = 0, af0 = 0, af1 = 0, ag0 = 0, ag1 = 0, ao0 = 0, ao1 = 0;
#pragma unroll 8
        for (int k = 0; k < 512; k++) {
            const u64* hp = (const u64*)&hs[(k << 6) + b0];
            u64 h01 = hp[0], h23 = hp[1];
            float4 wv = *(const float4*)&wp[k << 2];
            u64 wi = dup2(wv.x), wf = dup2(wv.y), wg = dup2(wv.z), wo = dup2(wv.w);
            fma2(ai0, h01, wi); fma2(ai1, h23, wi);
            fma2(af0, h01, wf); fma2(af1, h23, wf);
            fma2(ag0, h01, wg); fma2(ag1, h23, wg);
            fma2(ao0, h01, wo); fma2(ao1, h23, wo);
        }

        float2 i01 = unpk(ai0), i23 = unpk(ai1);
        float2 f01 = unpk(af0), f23 = unpk(af1);
        float2 g01 = unpk(ag0), g23 = unpk(ag1);
        float2 o01 = unpk(ao0), o23 = unpk(ao1);

        float4 hv;
        { float ig = sigm(i01.x + xpa.x), fg = sigm(f01.x + xpa.y);
          float gv = tanhf(g01.x + xpa.z), og = sigm(o01.x + xpa.w);
          c0 = fg * c0 + ig * gv; hv.x = og * tanhf(c0); }
        { float ig = sigm(i01.y + xpb.x), fg = sigm(f01.y + xpb.y);
          float gv = tanhf(g01.y + xpb.z), og = sigm(o01.y + xpb.w);
          c1 = fg * c1 + ig * gv; hv.y = og * tanhf(c1); }
        { float ig = sigm(i23.x + xpc.x), fg = sigm(f23.x + xpc.y);
          float gv = tanhf(g23.x + xpc.z), og = sigm(o23.x + xpc.w);
          c2 = fg * c2 + ig * gv; hv.z = og * tanhf(c2); }
        { float ig = sigm(i23.y + xpd.x), fg = sigm(f23.y + xpd.y);
          float gv = tanhf(g23.y + xpd.z), og = sigm(o23.y + xpd.w);
          c3 = fg * c3 + ig * gv; hv.w = og * tanhf(c3); }

        *(float4*)&g_h[dir][ph ^ 1][u][b0] = hv;

        __syncthreads();                 // all reads of hs + writes of h done
        if (threadIdx.x == 0) {
            __threadfence();             // release h writes
            atomicAdd(&g_bar_enc, 1u);
            unsigned target = (unsigned)(t + 1) * gridDim.x;
            while (*(volatile unsigned*)&g_bar_enc < target) {}
            __threadfence();             // acquire
        }
        __syncthreads();
    }
}

// ---------------- decoder constant input projection ----------------
__global__ void __launch_bounds__(128) xp0_kernel()
{
    const int w = threadIdx.x >> 5;
    const int l = threadIdx.x & 31;
    const int f = blockIdx.x * 2 + (w >> 1);
    const int b = (w & 1) * 32 + l;

    __shared__ float hsx[64][64];
    __shared__ float wsx[2][64][4];

    float acc[4] = {0.0f, 0.0f, 0.0f, 0.0f};

    for (int k0 = 0; k0 < DECIN; k0 += 64) {
        const float* hsrc = (k0 < E_) ? &g_h[0][0][k0][0] : &g_h[1][0][k0 - E_][0];
        {
            const float4* src = (const float4*)hsrc;
            float4* dst = (float4*)hsx;
            for (int i = threadIdx.x; i < 1024; i += 128) dst[i] = src[i];
        }
        {
            int idx = threadIdx.x;
            int uu = idx >> 6, kk = idx & 63;
            ((float4*)wsx)[idx] = *(const float4*)&g_WdecIhIl[blockIdx.x * 2 + uu][k0 + kk][0];
        }
        __syncthreads();
#pragma unroll 16
        for (int kk = 0; kk < 64; kk++) {
            float hv = hsx[kk][b];
            float4 wv = *(const float4*)&wsx[w >> 1][kk][0];
            acc[0] += hv * wv.x; acc[1] += hv * wv.y;
            acc[2] += hv * wv.z; acc[3] += hv * wv.w;
        }
        __syncthreads();
    }

    float4 r;
    r.x = acc[0] + g_bdecIl[f][0];
    r.y = acc[1] + g_bdecIl[f][1];
    r.z = acc[2] + g_bdecIl[f][2];
    r.w = acc[3] + g_bdecIl[f][3];
    *(float4*)&g_xp0[b][f][0] = r;
}

// ---------------- persistent decoder: all 512 steps, grid barrier ----------------
// grid = 128 CTAs (2 f-units each), 128 threads; warp = (unit, batch-half).
// dynamic smem: ws 8KB (Whh slice, once) + hs 64KB (full h per step).
__global__ void __launch_bounds__(128) dec_persist(float* __restrict__ out)
{
    extern __shared__ float sm[];
    float* ws = sm;            // 2 * 256 * 4 = 2048 floats
    float* hs = sm + 2048;     // 256 * 64 = 16384 floats

    const int w = threadIdx.x >> 5;
    const int l = threadIdx.x & 31;
    const int f = blockIdx.x * 2 + (w >> 1);
    const int b = (w & 1) * 32 + l;

    for (int i = threadIdx.x; i < 512; i += 128) {
        int su = i >> 8, k = i & 255;
        ((float4*)ws)[i] = *(const float4*)&g_WdecHhIl[blockIdx.x * 2 + su][k][0];
    }

    const float* wp = ws + (w >> 1) * 1024;
    float c = 0.f;
    const float4 xp = *(const float4*)&g_xp0[b][f][0];   // constant across steps

    for (int t = 0; t < T_; t++) {
        const int ph = t & 1;
        const float4* hsrc = (const float4*)&g_hd[ph][0][0];
        for (int i = threadIdx.x; i < 4096; i += 128)
            ((float4*)hs)[i] = __ldcg(hsrc + i);
        __syncthreads();

        u64 a_if = 0, a_go = 0;
#pragma unroll 8
        for (int k = 0; k < 256; k++) {
            u64 hd = dup2(hs[(k << 6) + b]);
            const u64* wq = (const u64*)&wp[k << 2];
            fma2(a_if, hd, wq[0]);
            fma2(a_go, hd, wq[1]);
        }
        float2 vif = unpk(a_if), vgo = unpk(a_go);
        float ig = sigm(vif.x + xp.x), fg = sigm(vif.y + xp.y);
        float gv = tanhf(vgo.x + xp.z), og = sigm(vgo.y + xp.w);
        c = fg * c + ig * gv;
        float h = og * tanhf(c);
        g_hd[ph ^ 1][f][b] = h;
        out[((size_t)t * B_ + b) * F_ + f] = h;

        __syncthreads();
        if (threadIdx.x == 0) {
            __threadfence();
            atomicAdd(&g_bar_dec, 1u);
            unsigned target = (unsigned)(t + 1) * gridDim.x;
            while (*(volatile unsigned*)&g_bar_dec < target) {}
            __threadfence();
        }
        __syncthreads();
    }
}

// ---------------- launch: 5 graph nodes total ----------------
extern "C" void kernel_launch(void* const* d_in, const int* in_sizes, int n_in,
                              void* d_out, int out_size)
{
    const float* seq  = (const float*)d_in[0];
    const float* wihf = (const float*)d_in[1];
    const float* whhf = (const float*)d_in[2];
    const float* bf   = (const float*)d_in[3];
    const float* wihb = (const float*)d_in[4];
    const float* whhb = (const float*)d_in[5];
    const float* bb   = (const float*)d_in[6];
    const float* dwih = (const float*)d_in[7];
    const float* dwhh = (const float*)d_in[8];
    const float* db   = (const float*)d_in[9];
    float* out = (float*)d_out;

    cudaFuncSetAttribute(enc_persist, cudaFuncAttributeMaxDynamicSharedMemorySize, 196608);
    cudaFuncSetAttribute(dec_persist, cudaFuncAttributeMaxDynamicSharedMemorySize, 73728);

    prep_kernel<<<1024, 256>>>(wihf, whhf, bf, wihb, whhb, bb, dwih, dwhh, db);

    dim3 g(G4E / 64, 32768 / 128, 2);
    xproj_gemm<<<g, 256>>>(seq);

    enc_persist<<<128, 128, 196608>>>();

    xp0_kernel<<<128, 128>>>();

    dec_persist<<<128, 128, 73728>>>(out);
}